// round 4
// baseline (speedup 1.0000x reference)
#include <cuda_runtime.h>
#include <cuda_bf16.h>
#include <math.h>
#include <stdint.h>

// Problem dims
#define BATCH 2
#define SEQ   2048
#define DIM   2048
#define NSTATE 16
#define TOKENS (BATCH*SEQ)        // 4096
#define TWO_DIM (2*DIM)           // 4096
#define LN_EPS 1e-5f

// -------------------- scratch (device globals, allocation-free) ------------
__device__ float g_xn[TOKENS * DIM];
__device__ float g_xz[TOKENS * TWO_DIM];
__device__ float g_dt[TOKENS * DIM];
__device__ float g_gated[TOKENS * DIM];
__device__ float g_win [TWO_DIM * DIM];
__device__ float g_wdt [DIM * DIM];
__device__ float g_wout[DIM * DIM];

// -------------------- helpers ----------------------------------------------
__device__ __forceinline__ float to_tf32(float x) {
    float y;
    asm("cvt.rna.tf32.f32 %0, %1;" : "=f"(y) : "f"(x));
    return y;
}
__device__ __forceinline__ void cp_async16(void* smem, const void* gmem) {
    unsigned s = (unsigned)__cvta_generic_to_shared(smem);
    asm volatile("cp.async.cg.shared.global [%0], [%1], 16;\n" :: "r"(s), "l"(gmem));
}
__device__ __forceinline__ void mma_tf32(float* c, const unsigned* a, const unsigned* b) {
    asm volatile(
        "mma.sync.aligned.m16n8k8.row.col.f32.tf32.tf32.f32 "
        "{%0,%1,%2,%3}, {%4,%5,%6,%7}, {%8,%9}, {%0,%1,%2,%3};"
        : "+f"(c[0]), "+f"(c[1]), "+f"(c[2]), "+f"(c[3])
        : "r"(a[0]), "r"(a[1]), "r"(a[2]), "r"(a[3]), "r"(b[0]), "r"(b[1]));
}

// -------------------- TF32 tensor-core GEMM (C = A @ B^T + bias [+epi]) -----
// A: MxK row-major (lda), B: NxK row-major (ldb)  ->  mma row.col directly.
// Block tile 256x128, BK=16, 512 threads, warp tile 64x32, 3-stage cp.async.
// EPI: 0 = bias; 1 = min(softplus(v),1); 2 = bias + residual.  RND: tf32 out.
#define BM 256
#define BN 128
#define BK 16
#define STAGES 3
#define SPAD 20   // smem row stride (floats); fragment LDS conflict-free

template<int EPI, int RND>
__global__ void __launch_bounds__(512, 1) gemm_tf32(
    const float* __restrict__ A, int lda,
    const float* __restrict__ B, int ldb,
    const float* __restrict__ bias,
    const float* __restrict__ res, int ldres,
    float* __restrict__ C, int ldc,
    int K)
{
    __shared__ float As[STAGES][BM][SPAD];
    __shared__ float Bs[STAGES][BN][SPAD];

    const int bm = blockIdx.y * BM;
    const int bn = blockIdx.x * BN;
    const int tid = threadIdx.x;
    const int wid = tid >> 5;
    const int lane = tid & 31;
    const int g = lane >> 2;       // 0..7
    const int t = lane & 3;        // 0..3

    const int warp_m = wid >> 2;   // 0..3
    const int warp_n = wid & 3;    // 0..3
    const int m0 = warp_m * 64;
    const int n0 = warp_n * 32;

    // load mapping:
    // A tile: 256 rows x 16 floats = 1024 float4 -> 2 per thread
    const int ar = tid >> 1;             // 0..255
    const int ac = (tid & 1) * 8;        // 0 or 8 (floats)
    // B tile: 128 rows x 16 floats = 512 float4 -> 1 per thread
    const int br = tid >> 2;             // 0..127
    const int bc = (tid & 3) * 4;        // 0,4,8,12

    const float* Ag = A + (size_t)(bm + ar) * lda + ac;
    const float* Bg = B + (size_t)(bn + br) * ldb + bc;

    float acc[4][4][4];
    #pragma unroll
    for (int i = 0; i < 4; i++)
        #pragma unroll
        for (int j = 0; j < 4; j++)
            #pragma unroll
            for (int r = 0; r < 4; r++) acc[i][j][r] = 0.f;

    const int NCH = K / BK;

    // prologue: stages 0,1
    #pragma unroll
    for (int c = 0; c < STAGES - 1; c++) {
        cp_async16(&As[c][ar][ac],     Ag + c * BK);
        cp_async16(&As[c][ar][ac + 4], Ag + c * BK + 4);
        cp_async16(&Bs[c][br][bc],     Bg + c * BK);
        asm volatile("cp.async.commit_group;\n" ::: "memory");
    }

    int cur = 0;
    for (int k = 0; k < NCH; k++) {
        asm volatile("cp.async.wait_group %0;\n" :: "n"(STAGES - 2) : "memory");
        __syncthreads();

        // issue stage k+2 right after the barrier (max overlap)
        const int j = k + STAGES - 1;
        if (j < NCH) {
            const int s = (cur + STAGES - 1 >= STAGES) ? cur - 1 : cur + STAGES - 1;
            cp_async16(&As[s][ar][ac],     Ag + j * BK);
            cp_async16(&As[s][ar][ac + 4], Ag + j * BK + 4);
            cp_async16(&Bs[s][br][bc],     Bg + j * BK);
        }
        asm volatile("cp.async.commit_group;\n" ::: "memory");

        #pragma unroll
        for (int kk = 0; kk < BK; kk += 8) {
            unsigned af[4][4], bf[4][2];
            #pragma unroll
            for (int mt = 0; mt < 4; mt++) {
                const int m = m0 + mt * 16;
                af[mt][0] = __float_as_uint(As[cur][m + g][kk + t]);
                af[mt][1] = __float_as_uint(As[cur][m + g + 8][kk + t]);
                af[mt][2] = __float_as_uint(As[cur][m + g][kk + t + 4]);
                af[mt][3] = __float_as_uint(As[cur][m + g + 8][kk + t + 4]);
            }
            #pragma unroll
            for (int nt = 0; nt < 4; nt++) {
                const int n = n0 + nt * 8;
                bf[nt][0] = __float_as_uint(Bs[cur][n + g][kk + t]);
                bf[nt][1] = __float_as_uint(Bs[cur][n + g][kk + t + 4]);
            }
            #pragma unroll
            for (int mt = 0; mt < 4; mt++)
                #pragma unroll
                for (int nt = 0; nt < 4; nt++)
                    mma_tf32(acc[mt][nt], af[mt], bf[nt]);
        }
        cur = (cur + 1 == STAGES) ? 0 : cur + 1;
    }

    // epilogue
    #pragma unroll
    for (int mt = 0; mt < 4; mt++) {
        const int row0 = bm + m0 + mt * 16 + g;
        #pragma unroll
        for (int nt = 0; nt < 4; nt++) {
            const int col = bn + n0 + nt * 8 + 2 * t;
            const float bv0 = bias[col], bv1 = bias[col + 1];
            float v00 = acc[mt][nt][0] + bv0;
            float v01 = acc[mt][nt][1] + bv1;
            float v10 = acc[mt][nt][2] + bv0;
            float v11 = acc[mt][nt][3] + bv1;
            if (EPI == 1) {
                v00 = fminf((v00 > 20.f) ? v00 : log1pf(__expf(v00)), 1.0f);
                v01 = fminf((v01 > 20.f) ? v01 : log1pf(__expf(v01)), 1.0f);
                v10 = fminf((v10 > 20.f) ? v10 : log1pf(__expf(v10)), 1.0f);
                v11 = fminf((v11 > 20.f) ? v11 : log1pf(__expf(v11)), 1.0f);
            } else if (EPI == 2) {
                v00 += res[(size_t)row0 * ldres + col];
                v01 += res[(size_t)row0 * ldres + col + 1];
                v10 += res[(size_t)(row0 + 8) * ldres + col];
                v11 += res[(size_t)(row0 + 8) * ldres + col + 1];
            }
            if (RND) {
                v00 = to_tf32(v00); v01 = to_tf32(v01);
                v10 = to_tf32(v10); v11 = to_tf32(v11);
            }
            *(float2*)(C + (size_t)row0 * ldc + col)       = make_float2(v00, v01);
            *(float2*)(C + (size_t)(row0 + 8) * ldc + col) = make_float2(v10, v11);
        }
    }
}

// -------------------- weight tf32 rounding ---------------------------------
__global__ void __launch_bounds__(256) round_kernel(
    const float4* __restrict__ src, float4* __restrict__ dst, int n4)
{
    int i = blockIdx.x * blockDim.x + threadIdx.x;
    int stride = gridDim.x * blockDim.x;
    for (; i < n4; i += stride) {
        float4 v = src[i];
        v.x = to_tf32(v.x); v.y = to_tf32(v.y);
        v.z = to_tf32(v.z); v.w = to_tf32(v.w);
        dst[i] = v;
    }
}

// -------------------- LayerNorm (tf32-rounded output) -----------------------
__global__ void __launch_bounds__(256) ln_kernel(
    const float* __restrict__ x,
    const float* __restrict__ gamma,
    const float* __restrict__ beta,
    float* __restrict__ out)
{
    const int token = blockIdx.x;
    const float* xp = x + (size_t)token * DIM;
    float* op = out + (size_t)token * DIM;
    const int base = threadIdx.x * 8;

    float4 a = *(const float4*)(xp + base);
    float4 b = *(const float4*)(xp + base + 4);

    float s  = a.x + a.y + a.z + a.w + b.x + b.y + b.z + b.w;
    float ss = a.x*a.x + a.y*a.y + a.z*a.z + a.w*a.w
             + b.x*b.x + b.y*b.y + b.z*b.z + b.w*b.w;

    #pragma unroll
    for (int o = 16; o > 0; o >>= 1) {
        s  += __shfl_down_sync(0xffffffffu, s,  o);
        ss += __shfl_down_sync(0xffffffffu, ss, o);
    }
    __shared__ float sbuf[8], ssbuf[8];
    const int warp = threadIdx.x >> 5, lane = threadIdx.x & 31;
    if (lane == 0) { sbuf[warp] = s; ssbuf[warp] = ss; }
    __syncthreads();
    __shared__ float s_mean, s_rstd;
    if (threadIdx.x == 0) {
        float ts = 0.f, tss = 0.f;
        #pragma unroll
        for (int w = 0; w < 8; w++) { ts += sbuf[w]; tss += ssbuf[w]; }
        float mean = ts * (1.0f / DIM);
        float var  = tss * (1.0f / DIM) - mean * mean;
        s_mean = mean;
        s_rstd = rsqrtf(var + LN_EPS);
    }
    __syncthreads();
    const float mean = s_mean, rstd = s_rstd;

    float4 g0 = *(const float4*)(gamma + base);
    float4 g1 = *(const float4*)(gamma + base + 4);
    float4 bt0 = *(const float4*)(beta + base);
    float4 bt1 = *(const float4*)(beta + base + 4);

    float4 o0, o1;
    o0.x = to_tf32((a.x - mean) * rstd * g0.x + bt0.x);
    o0.y = to_tf32((a.y - mean) * rstd * g0.y + bt0.y);
    o0.z = to_tf32((a.z - mean) * rstd * g0.z + bt0.z);
    o0.w = to_tf32((a.w - mean) * rstd * g0.w + bt0.w);
    o1.x = to_tf32((b.x - mean) * rstd * g1.x + bt1.x);
    o1.y = to_tf32((b.y - mean) * rstd * g1.y + bt1.y);
    o1.z = to_tf32((b.z - mean) * rstd * g1.z + bt1.z);
    o1.w = to_tf32((b.w - mean) * rstd * g1.w + bt1.w);
    *(float4*)(op + base)     = o0;
    *(float4*)(op + base + 4) = o1;
}

// -------------------- fused B/C projection + SSM + gate ---------------------
__global__ void __launch_bounds__(256) bcssm_kernel(
    const float* __restrict__ xz, int ld,
    const float* __restrict__ dt,
    const float* __restrict__ A,
    const float* __restrict__ W_B, const float* __restrict__ b_B,
    const float* __restrict__ W_C, const float* __restrict__ b_C,
    float* __restrict__ gated)
{
    __shared__ float xs[DIM];
    __shared__ float coef[NSTATE];
    const int token = blockIdx.x;
    const float* xrow = xz + (size_t)token * ld;

    #pragma unroll
    for (int d = threadIdx.x * 4; d < DIM; d += 256 * 4)
        *(float4*)(xs + d) = *(const float4*)(xrow + d);
    __syncthreads();

    const int warp = threadIdx.x >> 5, lane = threadIdx.x & 31;
    const int n0 = warp * 2, n1 = n0 + 1;
    const float* wb0 = W_B + (size_t)n0 * DIM;
    const float* wb1 = W_B + (size_t)n1 * DIM;
    const float* wc0 = W_C + (size_t)n0 * DIM;
    const float* wc1 = W_C + (size_t)n1 * DIM;

    float sB0 = 0.f, sB1 = 0.f, sC0 = 0.f, sC1 = 0.f;
    for (int d = lane * 4; d < DIM; d += 128) {
        float4 xv  = *(const float4*)(xs + d);
        float4 vb0 = *(const float4*)(wb0 + d);
        float4 vb1 = *(const float4*)(wb1 + d);
        float4 vc0 = *(const float4*)(wc0 + d);
        float4 vc1 = *(const float4*)(wc1 + d);
        sB0 += xv.x*vb0.x + xv.y*vb0.y + xv.z*vb0.z + xv.w*vb0.w;
        sB1 += xv.x*vb1.x + xv.y*vb1.y + xv.z*vb1.z + xv.w*vb1.w;
        sC0 += xv.x*vc0.x + xv.y*vc0.y + xv.z*vc0.z + xv.w*vc0.w;
        sC1 += xv.x*vc1.x + xv.y*vc1.y + xv.z*vc1.z + xv.w*vc1.w;
    }
    #pragma unroll
    for (int o = 16; o > 0; o >>= 1) {
        sB0 += __shfl_down_sync(0xffffffffu, sB0, o);
        sB1 += __shfl_down_sync(0xffffffffu, sB1, o);
        sC0 += __shfl_down_sync(0xffffffffu, sC0, o);
        sC1 += __shfl_down_sync(0xffffffffu, sC1, o);
    }
    if (lane == 0) {
        coef[n0] = (sB0 + b_B[n0]) * (sC0 + b_C[n0]);
        coef[n1] = (sB1 + b_B[n1]) * (sC1 + b_C[n1]);
    }
    __syncthreads();

    float c[NSTATE];
    #pragma unroll
    for (int n = 0; n < NSTATE; n++) c[n] = coef[n];

    const float* zrow  = xrow + DIM;
    const float* dtrow = dt + (size_t)token * DIM;
    float* grow = gated + (size_t)token * DIM;

    for (int d = threadIdx.x; d < DIM; d += 256) {
        const float dtd = dtrow[d];
        float s = 0.f;
        #pragma unroll
        for (int n = 0; n < NSTATE; n++)
            s += c[n] * __expf(A[n * DIM + d] * dtd);
        const float xv = xs[d];
        const float zv = zrow[d];
        const float sig = 1.0f / (1.0f + __expf(-zv));
        grow[d] = to_tf32(s * xv * zv * sig);
    }
}

// -------------------- launch ------------------------------------------------
extern "C" void kernel_launch(void* const* d_in, const int* in_sizes, int n_in,
                              void* d_out, int out_size)
{
    const float* x        = (const float*)d_in[0];
    const float* ln_gamma = (const float*)d_in[1];
    const float* ln_beta  = (const float*)d_in[2];
    const float* W_in     = (const float*)d_in[3];
    const float* b_in     = (const float*)d_in[4];
    const float* state_A  = (const float*)d_in[5];
    const float* W_B      = (const float*)d_in[6];
    const float* b_B      = (const float*)d_in[7];
    const float* W_C      = (const float*)d_in[8];
    const float* b_C      = (const float*)d_in[9];
    const float* W_dt     = (const float*)d_in[10];
    const float* b_dt     = (const float*)d_in[11];
    const float* W_out    = (const float*)d_in[12];
    const float* b_out    = (const float*)d_in[13];
    float* out = (float*)d_out;

    float *xn, *xz, *dt, *gated, *win, *wdt, *wout;
    cudaGetSymbolAddress((void**)&xn,    g_xn);
    cudaGetSymbolAddress((void**)&xz,    g_xz);
    cudaGetSymbolAddress((void**)&dt,    g_dt);
    cudaGetSymbolAddress((void**)&gated, g_gated);
    cudaGetSymbolAddress((void**)&win,   g_win);
    cudaGetSymbolAddress((void**)&wdt,   g_wdt);
    cudaGetSymbolAddress((void**)&wout,  g_wout);

    // 0. round weights to tf32
    round_kernel<<<1024, 256>>>((const float4*)W_in,  (float4*)win,  TWO_DIM * DIM / 4);
    round_kernel<<<512,  256>>>((const float4*)W_dt,  (float4*)wdt,  DIM * DIM / 4);
    round_kernel<<<512,  256>>>((const float4*)W_out, (float4*)wout, DIM * DIM / 4);

    // 1. LayerNorm (tf32 output)
    ln_kernel<<<TOKENS, 256>>>(x, ln_gamma, ln_beta, xn);

    // 2. xz = xn @ W_in^T + b_in   (M=4096, N=4096, K=2048), round output
    gemm_tf32<0, 1><<<dim3(TWO_DIM / BN, TOKENS / BM), 512>>>(
        xn, DIM, win, DIM, b_in, nullptr, 0, xz, TWO_DIM, DIM);

    // 3. dt = min(softplus(x_ssm @ W_dt^T + b_dt), 1)   (N=2048)
    gemm_tf32<1, 0><<<dim3(DIM / BN, TOKENS / BM), 512>>>(
        xz, TWO_DIM, wdt, DIM, b_dt, nullptr, 0, dt, DIM, DIM);

    // 4+5. coef + gated fused
    bcssm_kernel<<<TOKENS, 256>>>(xz, TWO_DIM, dt, state_A, W_B, b_B, W_C, b_C, gated);

    // 6. out = gated @ W_out^T + b_out + residual(x)
    gemm_tf32<2, 0><<<dim3(DIM / BN, TOKENS / BM), 512>>>(
        gated, DIM, wout, DIM, b_out, x, DIM, out, DIM, DIM);
}

// round 5
// speedup vs baseline: 1.1626x; 1.1626x over previous
#include <cuda_runtime.h>
#include <cuda_bf16.h>
#include <math.h>
#include <stdint.h>

// Problem dims
#define BATCH 2
#define SEQ   2048
#define DIM   2048
#define NSTATE 16
#define TOKENS (BATCH*SEQ)        // 4096
#define TWO_DIM (2*DIM)           // 4096
#define LN_EPS 1e-5f

// -------------------- scratch (device globals, allocation-free) ------------
__device__ float g_xn[TOKENS * DIM];
__device__ float g_xz[TOKENS * TWO_DIM];
__device__ float g_dt[TOKENS * DIM];
__device__ float g_gated[TOKENS * DIM];
__device__ float g_win [TWO_DIM * DIM];
__device__ float g_wdt [DIM * DIM];
__device__ float g_wout[DIM * DIM];

// -------------------- helpers ----------------------------------------------
__device__ __forceinline__ float to_tf32(float x) {
    float y;
    asm("cvt.rna.tf32.f32 %0, %1;" : "=f"(y) : "f"(x));
    return y;
}
__device__ __forceinline__ void cp_async16(void* smem, const void* gmem) {
    unsigned s = (unsigned)__cvta_generic_to_shared(smem);
    asm volatile("cp.async.cg.shared.global [%0], [%1], 16;\n" :: "r"(s), "l"(gmem));
}
__device__ __forceinline__ void mma_tf32(float* c, const unsigned* a, const unsigned* b) {
    asm volatile(
        "mma.sync.aligned.m16n8k8.row.col.f32.tf32.tf32.f32 "
        "{%0,%1,%2,%3}, {%4,%5,%6,%7}, {%8,%9}, {%0,%1,%2,%3};"
        : "+f"(c[0]), "+f"(c[1]), "+f"(c[2]), "+f"(c[3])
        : "r"(a[0]), "r"(a[1]), "r"(a[2]), "r"(a[3]), "r"(b[0]), "r"(b[1]));
}

// -------------------- TF32 tensor-core GEMM (C = A @ B^T + bias [+epi]) -----
// A: MxK row-major (lda), B: NxK row-major (ldb)  ->  mma row.col directly.
// Block tile 128x128, BK=16, 256 threads, warp tile 64x32.
// 3-stage cp.async ring, ONE __syncthreads per iteration, 2 CTAs/SM.
// EPI: 0 = bias; 1 = min(softplus(v),1); 2 = bias + residual.  RND: tf32 out.
#define BM 128
#define BN 128
#define BK 16
#define STAGES 3
#define SPAD 20   // smem row stride (floats); fragment LDS conflict-free

template<int EPI, int RND>
__global__ void __launch_bounds__(256, 2) gemm_tf32(
    const float* __restrict__ A, int lda,
    const float* __restrict__ B, int ldb,
    const float* __restrict__ bias,
    const float* __restrict__ res, int ldres,
    float* __restrict__ C, int ldc,
    int K)
{
    __shared__ float As[STAGES][BM][SPAD];
    __shared__ float Bs[STAGES][BN][SPAD];

    const int bm = blockIdx.y * BM;
    const int bn = blockIdx.x * BN;
    const int tid = threadIdx.x;
    const int wid = tid >> 5;
    const int lane = tid & 31;
    const int g = lane >> 2;       // 0..7
    const int t = lane & 3;        // 0..3

    const int warp_m = wid >> 2;   // 0..1
    const int warp_n = wid & 3;    // 0..3
    const int m0 = warp_m * 64;
    const int n0 = warp_n * 32;

    // load mapping: each tile is 128 rows x 16 floats = 512 float4; 2/thread
    const int lrow = tid >> 2;           // 0..63
    const int lcol = (tid & 3) << 2;     // 0,4,8,12

    const float* Ag = A + (size_t)(bm + lrow) * lda + lcol;
    const float* Bg = B + (size_t)(bn + lrow) * ldb + lcol;

    float acc[4][4][4];
    #pragma unroll
    for (int i = 0; i < 4; i++)
        #pragma unroll
        for (int j = 0; j < 4; j++)
            #pragma unroll
            for (int r = 0; r < 4; r++) acc[i][j][r] = 0.f;

    const int NCH = K / BK;

    // prologue: stages 0,1
    #pragma unroll
    for (int c = 0; c < STAGES - 1; c++) {
        cp_async16(&As[c][lrow][lcol],      Ag + c * BK);
        cp_async16(&As[c][lrow + 64][lcol], Ag + c * BK + (size_t)64 * lda);
        cp_async16(&Bs[c][lrow][lcol],      Bg + c * BK);
        cp_async16(&Bs[c][lrow + 64][lcol], Bg + c * BK + (size_t)64 * ldb);
        asm volatile("cp.async.commit_group;\n" ::: "memory");
    }

    int cur = 0, nxt = STAGES - 1;
    for (int k = 0; k < NCH; k++) {
        asm volatile("cp.async.wait_group %0;\n" :: "n"(STAGES - 2) : "memory");
        __syncthreads();

        // issue chunk k+2 into stage nxt (== (k-1)%3, proven drained by the sync)
        const int j = k + STAGES - 1;
        if (j < NCH) {
            cp_async16(&As[nxt][lrow][lcol],      Ag + j * BK);
            cp_async16(&As[nxt][lrow + 64][lcol], Ag + j * BK + (size_t)64 * lda);
            cp_async16(&Bs[nxt][lrow][lcol],      Bg + j * BK);
            cp_async16(&Bs[nxt][lrow + 64][lcol], Bg + j * BK + (size_t)64 * ldb);
        }
        asm volatile("cp.async.commit_group;\n" ::: "memory");

        #pragma unroll
        for (int kk = 0; kk < BK; kk += 8) {
            unsigned af[4][4], bf[4][2];
            #pragma unroll
            for (int mt = 0; mt < 4; mt++) {
                const int m = m0 + mt * 16;
                af[mt][0] = __float_as_uint(As[cur][m + g][kk + t]);
                af[mt][1] = __float_as_uint(As[cur][m + g + 8][kk + t]);
                af[mt][2] = __float_as_uint(As[cur][m + g][kk + t + 4]);
                af[mt][3] = __float_as_uint(As[cur][m + g + 8][kk + t + 4]);
            }
            #pragma unroll
            for (int nt = 0; nt < 4; nt++) {
                const int n = n0 + nt * 8;
                bf[nt][0] = __float_as_uint(Bs[cur][n + g][kk + t]);
                bf[nt][1] = __float_as_uint(Bs[cur][n + g][kk + t + 4]);
            }
            #pragma unroll
            for (int mt = 0; mt < 4; mt++)
                #pragma unroll
                for (int nt = 0; nt < 4; nt++)
                    mma_tf32(acc[mt][nt], af[mt], bf[nt]);
        }
        cur = (cur + 1 == STAGES) ? 0 : cur + 1;
        nxt = (nxt + 1 == STAGES) ? 0 : nxt + 1;
    }

    // epilogue
    #pragma unroll
    for (int mt = 0; mt < 4; mt++) {
        const int row0 = bm + m0 + mt * 16 + g;
        #pragma unroll
        for (int nt = 0; nt < 4; nt++) {
            const int col = bn + n0 + nt * 8 + 2 * t;
            const float bv0 = bias[col], bv1 = bias[col + 1];
            float v00 = acc[mt][nt][0] + bv0;
            float v01 = acc[mt][nt][1] + bv1;
            float v10 = acc[mt][nt][2] + bv0;
            float v11 = acc[mt][nt][3] + bv1;
            if (EPI == 1) {
                v00 = fminf((v00 > 20.f) ? v00 : log1pf(__expf(v00)), 1.0f);
                v01 = fminf((v01 > 20.f) ? v01 : log1pf(__expf(v01)), 1.0f);
                v10 = fminf((v10 > 20.f) ? v10 : log1pf(__expf(v10)), 1.0f);
                v11 = fminf((v11 > 20.f) ? v11 : log1pf(__expf(v11)), 1.0f);
            } else if (EPI == 2) {
                v00 += res[(size_t)row0 * ldres + col];
                v01 += res[(size_t)row0 * ldres + col + 1];
                v10 += res[(size_t)(row0 + 8) * ldres + col];
                v11 += res[(size_t)(row0 + 8) * ldres + col + 1];
            }
            if (RND) {
                v00 = to_tf32(v00); v01 = to_tf32(v01);
                v10 = to_tf32(v10); v11 = to_tf32(v11);
            }
            *(float2*)(C + (size_t)row0 * ldc + col)       = make_float2(v00, v01);
            *(float2*)(C + (size_t)(row0 + 8) * ldc + col) = make_float2(v10, v11);
        }
    }
}

// -------------------- weight tf32 rounding ---------------------------------
__global__ void __launch_bounds__(256) round_kernel(
    const float4* __restrict__ src, float4* __restrict__ dst, int n4)
{
    int i = blockIdx.x * blockDim.x + threadIdx.x;
    int stride = gridDim.x * blockDim.x;
    for (; i < n4; i += stride) {
        float4 v = src[i];
        v.x = to_tf32(v.x); v.y = to_tf32(v.y);
        v.z = to_tf32(v.z); v.w = to_tf32(v.w);
        dst[i] = v;
    }
}

// -------------------- LayerNorm (tf32-rounded output) -----------------------
__global__ void __launch_bounds__(256) ln_kernel(
    const float* __restrict__ x,
    const float* __restrict__ gamma,
    const float* __restrict__ beta,
    float* __restrict__ out)
{
    const int token = blockIdx.x;
    const float* xp = x + (size_t)token * DIM;
    float* op = out + (size_t)token * DIM;
    const int base = threadIdx.x * 8;

    float4 a = *(const float4*)(xp + base);
    float4 b = *(const float4*)(xp + base + 4);

    float s  = a.x + a.y + a.z + a.w + b.x + b.y + b.z + b.w;
    float ss = a.x*a.x + a.y*a.y + a.z*a.z + a.w*a.w
             + b.x*b.x + b.y*b.y + b.z*b.z + b.w*b.w;

    #pragma unroll
    for (int o = 16; o > 0; o >>= 1) {
        s  += __shfl_down_sync(0xffffffffu, s,  o);
        ss += __shfl_down_sync(0xffffffffu, ss, o);
    }
    __shared__ float sbuf[8], ssbuf[8];
    const int warp = threadIdx.x >> 5, lane = threadIdx.x & 31;
    if (lane == 0) { sbuf[warp] = s; ssbuf[warp] = ss; }
    __syncthreads();
    __shared__ float s_mean, s_rstd;
    if (threadIdx.x == 0) {
        float ts = 0.f, tss = 0.f;
        #pragma unroll
        for (int w = 0; w < 8; w++) { ts += sbuf[w]; tss += ssbuf[w]; }
        float mean = ts * (1.0f / DIM);
        float var  = tss * (1.0f / DIM) - mean * mean;
        s_mean = mean;
        s_rstd = rsqrtf(var + LN_EPS);
    }
    __syncthreads();
    const float mean = s_mean, rstd = s_rstd;

    float4 g0 = *(const float4*)(gamma + base);
    float4 g1 = *(const float4*)(gamma + base + 4);
    float4 bt0 = *(const float4*)(beta + base);
    float4 bt1 = *(const float4*)(beta + base + 4);

    float4 o0, o1;
    o0.x = to_tf32((a.x - mean) * rstd * g0.x + bt0.x);
    o0.y = to_tf32((a.y - mean) * rstd * g0.y + bt0.y);
    o0.z = to_tf32((a.z - mean) * rstd * g0.z + bt0.z);
    o0.w = to_tf32((a.w - mean) * rstd * g0.w + bt0.w);
    o1.x = to_tf32((b.x - mean) * rstd * g1.x + bt1.x);
    o1.y = to_tf32((b.y - mean) * rstd * g1.y + bt1.y);
    o1.z = to_tf32((b.z - mean) * rstd * g1.z + bt1.z);
    o1.w = to_tf32((b.w - mean) * rstd * g1.w + bt1.w);
    *(float4*)(op + base)     = o0;
    *(float4*)(op + base + 4) = o1;
}

// -------------------- fused B/C projection + SSM + gate ---------------------
__global__ void __launch_bounds__(256) bcssm_kernel(
    const float* __restrict__ xz, int ld,
    const float* __restrict__ dt,
    const float* __restrict__ A,
    const float* __restrict__ W_B, const float* __restrict__ b_B,
    const float* __restrict__ W_C, const float* __restrict__ b_C,
    float* __restrict__ gated)
{
    __shared__ float xs[DIM];
    __shared__ float coef[NSTATE];
    const int token = blockIdx.x;
    const float* xrow = xz + (size_t)token * ld;

    #pragma unroll
    for (int d = threadIdx.x * 4; d < DIM; d += 256 * 4)
        *(float4*)(xs + d) = *(const float4*)(xrow + d);
    __syncthreads();

    const int warp = threadIdx.x >> 5, lane = threadIdx.x & 31;
    const int n0 = warp * 2, n1 = n0 + 1;
    const float* wb0 = W_B + (size_t)n0 * DIM;
    const float* wb1 = W_B + (size_t)n1 * DIM;
    const float* wc0 = W_C + (size_t)n0 * DIM;
    const float* wc1 = W_C + (size_t)n1 * DIM;

    float sB0 = 0.f, sB1 = 0.f, sC0 = 0.f, sC1 = 0.f;
    for (int d = lane * 4; d < DIM; d += 128) {
        float4 xv  = *(const float4*)(xs + d);
        float4 vb0 = *(const float4*)(wb0 + d);
        float4 vb1 = *(const float4*)(wb1 + d);
        float4 vc0 = *(const float4*)(wc0 + d);
        float4 vc1 = *(const float4*)(wc1 + d);
        sB0 += xv.x*vb0.x + xv.y*vb0.y + xv.z*vb0.z + xv.w*vb0.w;
        sB1 += xv.x*vb1.x + xv.y*vb1.y + xv.z*vb1.z + xv.w*vb1.w;
        sC0 += xv.x*vc0.x + xv.y*vc0.y + xv.z*vc0.z + xv.w*vc0.w;
        sC1 += xv.x*vc1.x + xv.y*vc1.y + xv.z*vc1.z + xv.w*vc1.w;
    }
    #pragma unroll
    for (int o = 16; o > 0; o >>= 1) {
        sB0 += __shfl_down_sync(0xffffffffu, sB0, o);
        sB1 += __shfl_down_sync(0xffffffffu, sB1, o);
        sC0 += __shfl_down_sync(0xffffffffu, sC0, o);
        sC1 += __shfl_down_sync(0xffffffffu, sC1, o);
    }
    if (lane == 0) {
        coef[n0] = (sB0 + b_B[n0]) * (sC0 + b_C[n0]);
        coef[n1] = (sB1 + b_B[n1]) * (sC1 + b_C[n1]);
    }
    __syncthreads();

    float c[NSTATE];
    #pragma unroll
    for (int n = 0; n < NSTATE; n++) c[n] = coef[n];

    const float* zrow  = xrow + DIM;
    const float* dtrow = dt + (size_t)token * DIM;
    float* grow = gated + (size_t)token * DIM;

    for (int d = threadIdx.x; d < DIM; d += 256) {
        const float dtd = dtrow[d];
        float s = 0.f;
        #pragma unroll
        for (int n = 0; n < NSTATE; n++)
            s += c[n] * __expf(A[n * DIM + d] * dtd);
        const float xv = xs[d];
        const float zv = zrow[d];
        const float sig = 1.0f / (1.0f + __expf(-zv));
        grow[d] = to_tf32(s * xv * zv * sig);
    }
}

// -------------------- launch ------------------------------------------------
extern "C" void kernel_launch(void* const* d_in, const int* in_sizes, int n_in,
                              void* d_out, int out_size)
{
    const float* x        = (const float*)d_in[0];
    const float* ln_gamma = (const float*)d_in[1];
    const float* ln_beta  = (const float*)d_in[2];
    const float* W_in     = (const float*)d_in[3];
    const float* b_in     = (const float*)d_in[4];
    const float* state_A  = (const float*)d_in[5];
    const float* W_B      = (const float*)d_in[6];
    const float* b_B      = (const float*)d_in[7];
    const float* W_C      = (const float*)d_in[8];
    const float* b_C      = (const float*)d_in[9];
    const float* W_dt     = (const float*)d_in[10];
    const float* b_dt     = (const float*)d_in[11];
    const float* W_out    = (const float*)d_in[12];
    const float* b_out    = (const float*)d_in[13];
    float* out = (float*)d_out;

    float *xn, *xz, *dt, *gated, *win, *wdt, *wout;
    cudaGetSymbolAddress((void**)&xn,    g_xn);
    cudaGetSymbolAddress((void**)&xz,    g_xz);
    cudaGetSymbolAddress((void**)&dt,    g_dt);
    cudaGetSymbolAddress((void**)&gated, g_gated);
    cudaGetSymbolAddress((void**)&win,   g_win);
    cudaGetSymbolAddress((void**)&wdt,   g_wdt);
    cudaGetSymbolAddress((void**)&wout,  g_wout);

    // 0. round weights to tf32
    round_kernel<<<1024, 256>>>((const float4*)W_in,  (float4*)win,  TWO_DIM * DIM / 4);
    round_kernel<<<512,  256>>>((const float4*)W_dt,  (float4*)wdt,  DIM * DIM / 4);
    round_kernel<<<512,  256>>>((const float4*)W_out, (float4*)wout, DIM * DIM / 4);

    // 1. LayerNorm (tf32 output)
    ln_kernel<<<TOKENS, 256>>>(x, ln_gamma, ln_beta, xn);

    // 2. xz = xn @ W_in^T + b_in   (M=4096, N=4096, K=2048), round output
    gemm_tf32<0, 1><<<dim3(TWO_DIM / BN, TOKENS / BM), 256>>>(
        xn, DIM, win, DIM, b_in, nullptr, 0, xz, TWO_DIM, DIM);

    // 3. dt = min(softplus(x_ssm @ W_dt^T + b_dt), 1)   (N=2048)
    gemm_tf32<1, 0><<<dim3(DIM / BN, TOKENS / BM), 256>>>(
        xz, TWO_DIM, wdt, DIM, b_dt, nullptr, 0, dt, DIM, DIM);

    // 4+5. coef + gated fused
    bcssm_kernel<<<TOKENS, 256>>>(xz, TWO_DIM, dt, state_A, W_B, b_B, W_C, b_C, gated);

    // 6. out = gated @ W_out^T + b_out + residual(x)
    gemm_tf32<2, 0><<<dim3(DIM / BN, TOKENS / BM), 256>>>(
        gated, DIM, wout, DIM, b_out, x, DIM, out, DIM, DIM);
}

// round 6
// speedup vs baseline: 2.0438x; 1.7579x over previous
#include <cuda_runtime.h>
#include <cuda_fp16.h>
#include <math.h>
#include <stdint.h>

// Problem dims
#define BATCH 2
#define SEQ   2048
#define DIM   2048
#define NSTATE 16
#define TOKENS (BATCH*SEQ)        // 4096
#define TWO_DIM (2*DIM)           // 4096
#define LN_EPS 1e-5f

// -------------------- scratch (device globals, allocation-free) ------------
__device__ __half g_xn[TOKENS * DIM];
__device__ __half g_xz[TOKENS * TWO_DIM];
__device__ float  g_dt[TOKENS * DIM];
__device__ __half g_gated[TOKENS * DIM];
__device__ __half g_win [TWO_DIM * DIM];
__device__ __half g_wdt [DIM * DIM];
__device__ __half g_wout[DIM * DIM];

// -------------------- helpers ----------------------------------------------
__device__ __forceinline__ void cp_async16(void* smem, const void* gmem) {
    unsigned s = (unsigned)__cvta_generic_to_shared(smem);
    asm volatile("cp.async.cg.shared.global [%0], [%1], 16;\n" :: "r"(s), "l"(gmem));
}
__device__ __forceinline__ void mma_fp16(float* c, const unsigned* a, const unsigned* b) {
    asm volatile(
        "mma.sync.aligned.m16n8k16.row.col.f32.f16.f16.f32 "
        "{%0,%1,%2,%3}, {%4,%5,%6,%7}, {%8,%9}, {%0,%1,%2,%3};"
        : "+f"(c[0]), "+f"(c[1]), "+f"(c[2]), "+f"(c[3])
        : "r"(a[0]), "r"(a[1]), "r"(a[2]), "r"(a[3]), "r"(b[0]), "r"(b[1]));
}

// -------------------- FP16 tensor-core GEMM (C = A @ B^T + bias [+epi]) -----
// A: MxK row-major half (lda), B: NxK row-major half (ldb) -> mma row.col.
// Block tile 128x128, BK=32 halves, 256 threads, warp tile 64x32.
// 3-stage cp.async ring, one __syncthreads per iteration, 2 CTAs/SM.
// EPI: 0 = bias; 1 = min(softplus(v),1); 2 = bias + residual.
// OUTH: 1 = output __half, 0 = output float.
#define BM 128
#define BN 128
#define BKH 32                   // k-halves per iteration
#define STAGES 3
#define HROW 40                  // halves per smem row (pad 8): banks (20g+t)%32 bijective
#define TILE_H (BM * HROW)       // 5120 halves per tile per stage
#define SM_TOTAL_BYTES (2 * STAGES * TILE_H * 2)   // 61440

template<int EPI, int OUTH>
__global__ void __launch_bounds__(256, 2) gemm_fp16(
    const __half* __restrict__ A, int lda,
    const __half* __restrict__ B, int ldb,
    const float* __restrict__ bias,
    const float* __restrict__ res, int ldres,
    void* __restrict__ Cv, int ldc,
    int K)
{
    extern __shared__ __half sm[];
    // As: stages 0..2 at sm + s*TILE_H ; Bs: sm + 3*TILE_H + s*TILE_H
    #define AS(s, r, c) sm[(s) * TILE_H + (r) * HROW + (c)]
    #define BS(s, r, c) sm[STAGES * TILE_H + (s) * TILE_H + (r) * HROW + (c)]

    const int bm = blockIdx.y * BM;
    const int bn = blockIdx.x * BN;
    const int tid = threadIdx.x;
    const int wid = tid >> 5;
    const int lane = tid & 31;
    const int g = lane >> 2;       // 0..7
    const int t = lane & 3;        // 0..3

    const int warp_m = wid >> 2;   // 0..1
    const int warp_n = wid & 3;    // 0..3
    const int m0 = warp_m * 64;
    const int n0 = warp_n * 32;

    // loader: tile = 128 rows x 32 halves = 512 x 16B chunks; 2 chunks/thread
    const int ar = tid >> 2;             // 0..63
    const int ac = (tid & 3) * 8;        // half offset: 0,8,16,24

    const __half* Ag = A + (size_t)(bm + ar) * lda + ac;
    const __half* Bg = B + (size_t)(bn + ar) * ldb + ac;

    float acc[4][4][4];
    #pragma unroll
    for (int i = 0; i < 4; i++)
        #pragma unroll
        for (int j = 0; j < 4; j++)
            #pragma unroll
            for (int r = 0; r < 4; r++) acc[i][j][r] = 0.f;

    const int NCH = K / BKH;

    #pragma unroll
    for (int c = 0; c < STAGES - 1; c++) {
        cp_async16(&AS(c, ar, ac),      Ag + c * BKH);
        cp_async16(&AS(c, ar + 64, ac), Ag + c * BKH + (size_t)64 * lda);
        cp_async16(&BS(c, ar, ac),      Bg + c * BKH);
        cp_async16(&BS(c, ar + 64, ac), Bg + c * BKH + (size_t)64 * ldb);
        asm volatile("cp.async.commit_group;\n" ::: "memory");
    }

    int cur = 0, nxt = STAGES - 1;
    for (int k = 0; k < NCH; k++) {
        asm volatile("cp.async.wait_group %0;\n" :: "n"(STAGES - 2) : "memory");
        __syncthreads();

        const int j = k + STAGES - 1;
        if (j < NCH) {
            cp_async16(&AS(nxt, ar, ac),      Ag + j * BKH);
            cp_async16(&AS(nxt, ar + 64, ac), Ag + j * BKH + (size_t)64 * lda);
            cp_async16(&BS(nxt, ar, ac),      Bg + j * BKH);
            cp_async16(&BS(nxt, ar + 64, ac), Bg + j * BKH + (size_t)64 * ldb);
        }
        asm volatile("cp.async.commit_group;\n" ::: "memory");

        #pragma unroll
        for (int kk = 0; kk < BKH; kk += 16) {
            unsigned af[4][4], bf[4][2];
            #pragma unroll
            for (int mt = 0; mt < 4; mt++) {
                const int m = m0 + mt * 16;
                af[mt][0] = *(const unsigned*)&AS(cur, m + g,     kk + 2 * t);
                af[mt][1] = *(const unsigned*)&AS(cur, m + g + 8, kk + 2 * t);
                af[mt][2] = *(const unsigned*)&AS(cur, m + g,     kk + 2 * t + 8);
                af[mt][3] = *(const unsigned*)&AS(cur, m + g + 8, kk + 2 * t + 8);
            }
            #pragma unroll
            for (int nt = 0; nt < 4; nt++) {
                const int n = n0 + nt * 8;
                bf[nt][0] = *(const unsigned*)&BS(cur, n + g, kk + 2 * t);
                bf[nt][1] = *(const unsigned*)&BS(cur, n + g, kk + 2 * t + 8);
            }
            #pragma unroll
            for (int mt = 0; mt < 4; mt++)
                #pragma unroll
                for (int nt = 0; nt < 4; nt++)
                    mma_fp16(acc[mt][nt], af[mt], bf[nt]);
        }
        cur = (cur + 1 == STAGES) ? 0 : cur + 1;
        nxt = (nxt + 1 == STAGES) ? 0 : nxt + 1;
    }

    // epilogue
    #pragma unroll
    for (int mt = 0; mt < 4; mt++) {
        const int row0 = bm + m0 + mt * 16 + g;
        #pragma unroll
        for (int nt = 0; nt < 4; nt++) {
            const int col = bn + n0 + nt * 8 + 2 * t;
            const float bv0 = bias[col], bv1 = bias[col + 1];
            float v00 = acc[mt][nt][0] + bv0;
            float v01 = acc[mt][nt][1] + bv1;
            float v10 = acc[mt][nt][2] + bv0;
            float v11 = acc[mt][nt][3] + bv1;
            if (EPI == 1) {
                v00 = fminf((v00 > 20.f) ? v00 : log1pf(__expf(v00)), 1.0f);
                v01 = fminf((v01 > 20.f) ? v01 : log1pf(__expf(v01)), 1.0f);
                v10 = fminf((v10 > 20.f) ? v10 : log1pf(__expf(v10)), 1.0f);
                v11 = fminf((v11 > 20.f) ? v11 : log1pf(__expf(v11)), 1.0f);
            } else if (EPI == 2) {
                v00 += res[(size_t)row0 * ldres + col];
                v01 += res[(size_t)row0 * ldres + col + 1];
                v10 += res[(size_t)(row0 + 8) * ldres + col];
                v11 += res[(size_t)(row0 + 8) * ldres + col + 1];
            }
            if (OUTH) {
                __half* C = (__half*)Cv;
                *(__half2*)(C + (size_t)row0 * ldc + col)       = __floats2half2_rn(v00, v01);
                *(__half2*)(C + (size_t)(row0 + 8) * ldc + col) = __floats2half2_rn(v10, v11);
            } else {
                float* C = (float*)Cv;
                *(float2*)(C + (size_t)row0 * ldc + col)       = make_float2(v00, v01);
                *(float2*)(C + (size_t)(row0 + 8) * ldc + col) = make_float2(v10, v11);
            }
        }
    }
    #undef AS
    #undef BS
}

// -------------------- weight fp32 -> fp16 conversion ------------------------
__global__ void __launch_bounds__(256) cvt_kernel(
    const float4* __restrict__ src, __half* __restrict__ dst, int n4)
{
    int i = blockIdx.x * blockDim.x + threadIdx.x;
    int stride = gridDim.x * blockDim.x;
    for (; i < n4; i += stride) {
        float4 v = src[i];
        __half2 lo = __floats2half2_rn(v.x, v.y);
        __half2 hi = __floats2half2_rn(v.z, v.w);
        *(__half2*)(dst + i * 4)     = lo;
        *(__half2*)(dst + i * 4 + 2) = hi;
    }
}

// -------------------- LayerNorm (fp16 output) -------------------------------
__global__ void __launch_bounds__(256) ln_kernel(
    const float* __restrict__ x,
    const float* __restrict__ gamma,
    const float* __restrict__ beta,
    __half* __restrict__ out)
{
    const int token = blockIdx.x;
    const float* xp = x + (size_t)token * DIM;
    __half* op = out + (size_t)token * DIM;
    const int base = threadIdx.x * 8;

    float4 a = *(const float4*)(xp + base);
    float4 b = *(const float4*)(xp + base + 4);

    float s  = a.x + a.y + a.z + a.w + b.x + b.y + b.z + b.w;
    float ss = a.x*a.x + a.y*a.y + a.z*a.z + a.w*a.w
             + b.x*b.x + b.y*b.y + b.z*b.z + b.w*b.w;

    #pragma unroll
    for (int o = 16; o > 0; o >>= 1) {
        s  += __shfl_down_sync(0xffffffffu, s,  o);
        ss += __shfl_down_sync(0xffffffffu, ss, o);
    }
    __shared__ float sbuf[8], ssbuf[8];
    const int warp = threadIdx.x >> 5, lane = threadIdx.x & 31;
    if (lane == 0) { sbuf[warp] = s; ssbuf[warp] = ss; }
    __syncthreads();
    __shared__ float s_mean, s_rstd;
    if (threadIdx.x == 0) {
        float ts = 0.f, tss = 0.f;
        #pragma unroll
        for (int w = 0; w < 8; w++) { ts += sbuf[w]; tss += ssbuf[w]; }
        float mean = ts * (1.0f / DIM);
        float var  = tss * (1.0f / DIM) - mean * mean;
        s_mean = mean;
        s_rstd = rsqrtf(var + LN_EPS);
    }
    __syncthreads();
    const float mean = s_mean, rstd = s_rstd;

    float4 g0 = *(const float4*)(gamma + base);
    float4 g1 = *(const float4*)(gamma + base + 4);
    float4 bt0 = *(const float4*)(beta + base);
    float4 bt1 = *(const float4*)(beta + base + 4);

    __half2 h0 = __floats2half2_rn((a.x - mean) * rstd * g0.x + bt0.x,
                                   (a.y - mean) * rstd * g0.y + bt0.y);
    __half2 h1 = __floats2half2_rn((a.z - mean) * rstd * g0.z + bt0.z,
                                   (a.w - mean) * rstd * g0.w + bt0.w);
    __half2 h2 = __floats2half2_rn((b.x - mean) * rstd * g1.x + bt1.x,
                                   (b.y - mean) * rstd * g1.y + bt1.y);
    __half2 h3 = __floats2half2_rn((b.z - mean) * rstd * g1.z + bt1.z,
                                   (b.w - mean) * rstd * g1.w + bt1.w);
    uint4 pk;
    pk.x = *(unsigned*)&h0; pk.y = *(unsigned*)&h1;
    pk.z = *(unsigned*)&h2; pk.w = *(unsigned*)&h3;
    *(uint4*)(op + base) = pk;
}

// -------------------- fused B/C projection + SSM + gate ---------------------
__global__ void __launch_bounds__(256) bcssm_kernel(
    const __half* __restrict__ xz, int ld,
    const float* __restrict__ dt,
    const float* __restrict__ A,
    const float* __restrict__ W_B, const float* __restrict__ b_B,
    const float* __restrict__ W_C, const float* __restrict__ b_C,
    __half* __restrict__ gated)
{
    __shared__ float xs[DIM];
    __shared__ float coef[NSTATE];
    const int token = blockIdx.x;
    const __half* xrow = xz + (size_t)token * ld;

    // stage x_ssm row in smem as fp32
    for (int d = threadIdx.x * 8; d < DIM; d += 256 * 8) {
        uint4 pk = *(const uint4*)(xrow + d);
        float2 f0 = __half22float2(*(__half2*)&pk.x);
        float2 f1 = __half22float2(*(__half2*)&pk.y);
        float2 f2 = __half22float2(*(__half2*)&pk.z);
        float2 f3 = __half22float2(*(__half2*)&pk.w);
        xs[d+0] = f0.x; xs[d+1] = f0.y; xs[d+2] = f1.x; xs[d+3] = f1.y;
        xs[d+4] = f2.x; xs[d+5] = f2.y; xs[d+6] = f3.x; xs[d+7] = f3.y;
    }
    __syncthreads();

    const int warp = threadIdx.x >> 5, lane = threadIdx.x & 31;
    const int n0 = warp * 2, n1 = n0 + 1;
    const float* wb0 = W_B + (size_t)n0 * DIM;
    const float* wb1 = W_B + (size_t)n1 * DIM;
    const float* wc0 = W_C + (size_t)n0 * DIM;
    const float* wc1 = W_C + (size_t)n1 * DIM;

    float sB0 = 0.f, sB1 = 0.f, sC0 = 0.f, sC1 = 0.f;
    for (int d = lane * 4; d < DIM; d += 128) {
        float4 xv  = *(const float4*)(xs + d);
        float4 vb0 = *(const float4*)(wb0 + d);
        float4 vb1 = *(const float4*)(wb1 + d);
        float4 vc0 = *(const float4*)(wc0 + d);
        float4 vc1 = *(const float4*)(wc1 + d);
        sB0 += xv.x*vb0.x + xv.y*vb0.y + xv.z*vb0.z + xv.w*vb0.w;
        sB1 += xv.x*vb1.x + xv.y*vb1.y + xv.z*vb1.z + xv.w*vb1.w;
        sC0 += xv.x*vc0.x + xv.y*vc0.y + xv.z*vc0.z + xv.w*vc0.w;
        sC1 += xv.x*vc1.x + xv.y*vc1.y + xv.z*vc1.z + xv.w*vc1.w;
    }
    #pragma unroll
    for (int o = 16; o > 0; o >>= 1) {
        sB0 += __shfl_down_sync(0xffffffffu, sB0, o);
        sB1 += __shfl_down_sync(0xffffffffu, sB1, o);
        sC0 += __shfl_down_sync(0xffffffffu, sC0, o);
        sC1 += __shfl_down_sync(0xffffffffu, sC1, o);
    }
    if (lane == 0) {
        coef[n0] = (sB0 + b_B[n0]) * (sC0 + b_C[n0]);
        coef[n1] = (sB1 + b_B[n1]) * (sC1 + b_C[n1]);
    }
    __syncthreads();

    float c[NSTATE];
    #pragma unroll
    for (int n = 0; n < NSTATE; n++) c[n] = coef[n];

    const __half* zrow = xrow + DIM;
    const float* dtrow = dt + (size_t)token * DIM;
    __half* grow = gated + (size_t)token * DIM;

    for (int d = threadIdx.x; d < DIM; d += 256) {
        const float dtd = dtrow[d];
        float s = 0.f;
        #pragma unroll
        for (int n = 0; n < NSTATE; n++)
            s += c[n] * __expf(A[n * DIM + d] * dtd);
        const float xv = xs[d];
        const float zv = __half2float(zrow[d]);
        const float sig = 1.0f / (1.0f + __expf(-zv));
        grow[d] = __float2half_rn(s * xv * zv * sig);
    }
}

// -------------------- launch ------------------------------------------------
extern "C" void kernel_launch(void* const* d_in, const int* in_sizes, int n_in,
                              void* d_out, int out_size)
{
    const float* x        = (const float*)d_in[0];
    const float* ln_gamma = (const float*)d_in[1];
    const float* ln_beta  = (const float*)d_in[2];
    const float* W_in     = (const float*)d_in[3];
    const float* b_in     = (const float*)d_in[4];
    const float* state_A  = (const float*)d_in[5];
    const float* W_B      = (const float*)d_in[6];
    const float* b_B      = (const float*)d_in[7];
    const float* W_C      = (const float*)d_in[8];
    const float* b_C      = (const float*)d_in[9];
    const float* W_dt     = (const float*)d_in[10];
    const float* b_dt     = (const float*)d_in[11];
    const float* W_out    = (const float*)d_in[12];
    const float* b_out    = (const float*)d_in[13];
    float* out = (float*)d_out;

    __half *xn, *xz, *gated, *win, *wdt, *wout;
    float *dt;
    cudaGetSymbolAddress((void**)&xn,    g_xn);
    cudaGetSymbolAddress((void**)&xz,    g_xz);
    cudaGetSymbolAddress((void**)&dt,    g_dt);
    cudaGetSymbolAddress((void**)&gated, g_gated);
    cudaGetSymbolAddress((void**)&win,   g_win);
    cudaGetSymbolAddress((void**)&wdt,   g_wdt);
    cudaGetSymbolAddress((void**)&wout,  g_wout);

    static bool attr_done = false;
    if (!attr_done) {
        cudaFuncSetAttribute(gemm_fp16<0,1>, cudaFuncAttributeMaxDynamicSharedMemorySize, SM_TOTAL_BYTES);
        cudaFuncSetAttribute(gemm_fp16<1,0>, cudaFuncAttributeMaxDynamicSharedMemorySize, SM_TOTAL_BYTES);
        cudaFuncSetAttribute(gemm_fp16<2,0>, cudaFuncAttributeMaxDynamicSharedMemorySize, SM_TOTAL_BYTES);
        attr_done = true;
    }

    // 0. convert weights to fp16
    cvt_kernel<<<1024, 256>>>((const float4*)W_in,  win,  TWO_DIM * DIM / 4);
    cvt_kernel<<<512,  256>>>((const float4*)W_dt,  wdt,  DIM * DIM / 4);
    cvt_kernel<<<512,  256>>>((const float4*)W_out, wout, DIM * DIM / 4);

    // 1. LayerNorm (fp16 output)
    ln_kernel<<<TOKENS, 256>>>(x, ln_gamma, ln_beta, xn);

    // 2. xz = xn @ W_in^T + b_in   (M=4096, N=4096, K=2048) -> fp16
    gemm_fp16<0, 1><<<dim3(TWO_DIM / BN, TOKENS / BM), 256, SM_TOTAL_BYTES>>>(
        xn, DIM, win, DIM, b_in, nullptr, 0, xz, TWO_DIM, DIM);

    // 3. dt = min(softplus(x_ssm @ W_dt^T + b_dt), 1)  -> fp32
    gemm_fp16<1, 0><<<dim3(DIM / BN, TOKENS / BM), 256, SM_TOTAL_BYTES>>>(
        xz, TWO_DIM, wdt, DIM, b_dt, nullptr, 0, dt, DIM, DIM);

    // 4+5. coef + gated fused -> fp16
    bcssm_kernel<<<TOKENS, 256>>>(xz, TWO_DIM, dt, state_A, W_B, b_B, W_C, b_C, gated);

    // 6. out = gated @ W_out^T + b_out + residual(x) -> fp32
    gemm_fp16<2, 0><<<dim3(DIM / BN, TOKENS / BM), 256, SM_TOTAL_BYTES>>>(
        gated, DIM, wout, DIM, b_out, x, DIM, out, DIM, DIM);
}

// round 7
// speedup vs baseline: 2.1861x; 1.0696x over previous
#include <cuda_runtime.h>
#include <cuda_fp16.h>
#include <math.h>
#include <stdint.h>

// Problem dims
#define BATCH 2
#define SEQ   2048
#define DIM   2048
#define NSTATE 16
#define TOKENS (BATCH*SEQ)        // 4096
#define TWO_DIM (2*DIM)           // 4096
#define LN_EPS 1e-5f

// -------------------- scratch (device globals, allocation-free) ------------
__device__ __half g_xn[TOKENS * DIM];
__device__ __half g_xz[TOKENS * TWO_DIM];
__device__ __half g_dt[TOKENS * DIM];
__device__ __half g_gated[TOKENS * DIM];
__device__ __half g_win [TWO_DIM * DIM];
__device__ __half g_wdt [DIM * DIM];
__device__ __half g_wout[DIM * DIM];

// -------------------- helpers ----------------------------------------------
__device__ __forceinline__ void cp_async16(void* smem, const void* gmem) {
    unsigned s = (unsigned)__cvta_generic_to_shared(smem);
    asm volatile("cp.async.cg.shared.global [%0], [%1], 16;\n" :: "r"(s), "l"(gmem));
}
__device__ __forceinline__ void mma_fp16(float* c, const unsigned* a, const unsigned* b) {
    asm volatile(
        "mma.sync.aligned.m16n8k16.row.col.f32.f16.f16.f32 "
        "{%0,%1,%2,%3}, {%4,%5,%6,%7}, {%8,%9}, {%0,%1,%2,%3};"
        : "+f"(c[0]), "+f"(c[1]), "+f"(c[2]), "+f"(c[3])
        : "r"(a[0]), "r"(a[1]), "r"(a[2]), "r"(a[3]), "r"(b[0]), "r"(b[1]));
}
__device__ __forceinline__ void ldmatrix_x4(unsigned* r, unsigned saddr) {
    asm volatile("ldmatrix.sync.aligned.m8n8.x4.shared.b16 {%0,%1,%2,%3}, [%4];"
                 : "=r"(r[0]), "=r"(r[1]), "=r"(r[2]), "=r"(r[3]) : "r"(saddr));
}

// -------------------- FP16 tensor-core GEMM (C = A @ B^T + bias [+epi]) -----
// A: MxK row-major half (lda), B: NxK row-major half (ldb) -> mma row.col.
// Block tile 128x128, BK=32 halves, 256 threads, warp tile 64x32.
// 3-stage cp.async ring, one __syncthreads per iteration, 2 CTAs/SM.
// Fragment loads via ldmatrix (conflict-free with HROW=40 padding).
// EPI: 0 = bias; 1 = min(softplus(v),1); 2 = bias + residual.
// OUTH: 1 = output __half, 0 = output float.
#define BM 128
#define BN 128
#define BKH 32                   // k-halves per iteration
#define STAGES 3
#define HROW 40                  // halves per smem row (pad 8)
#define TILE_H (BM * HROW)       // 5120 halves per tile per stage
#define SM_TOTAL_BYTES (2 * STAGES * TILE_H * 2)   // 61440

template<int EPI, int OUTH>
__global__ void __launch_bounds__(256, 2) gemm_fp16(
    const __half* __restrict__ A, int lda,
    const __half* __restrict__ B, int ldb,
    const float* __restrict__ bias,
    const float* __restrict__ res, int ldres,
    void* __restrict__ Cv, int ldc,
    int K)
{
    extern __shared__ __half sm[];
    #define AS(s, r, c) sm[(s) * TILE_H + (r) * HROW + (c)]
    #define BS(s, r, c) sm[STAGES * TILE_H + (s) * TILE_H + (r) * HROW + (c)]

    const int bm = blockIdx.y * BM;
    const int bn = blockIdx.x * BN;
    const int tid = threadIdx.x;
    const int wid = tid >> 5;
    const int lane = tid & 31;
    const int g = lane >> 2;       // 0..7
    const int t = lane & 3;        // 0..3

    const int warp_m = wid >> 2;   // 0..1
    const int warp_n = wid & 3;    // 0..3
    const int m0 = warp_m * 64;
    const int n0 = warp_n * 32;

    // ldmatrix addressing
    const unsigned smem_base = (unsigned)__cvta_generic_to_shared(sm);
    const int lane16 = lane & 15;
    const int lhalf  = lane >> 4;          // 0 or 1
    unsigned aoff[4], boff[2];
    #pragma unroll
    for (int mt = 0; mt < 4; mt++)
        aoff[mt] = smem_base + ((m0 + mt * 16 + lane16) * HROW + lhalf * 8) * 2;
    #pragma unroll
    for (int np = 0; np < 2; np++)
        boff[np] = smem_base + (STAGES * TILE_H + (n0 + np * 16 + lane16) * HROW + lhalf * 8) * 2;

    // loader: tile = 128 rows x 32 halves = 512 x 16B chunks; 2 chunks/thread
    const int ar = tid >> 2;             // 0..63
    const int ac = (tid & 3) * 8;        // half offset: 0,8,16,24

    const __half* Ag = A + (size_t)(bm + ar) * lda + ac;
    const __half* Bg = B + (size_t)(bn + ar) * ldb + ac;

    float acc[4][4][4];
    #pragma unroll
    for (int i = 0; i < 4; i++)
        #pragma unroll
        for (int j = 0; j < 4; j++)
            #pragma unroll
            for (int r = 0; r < 4; r++) acc[i][j][r] = 0.f;

    const int NCH = K / BKH;

    #pragma unroll
    for (int c = 0; c < STAGES - 1; c++) {
        cp_async16(&AS(c, ar, ac),      Ag + c * BKH);
        cp_async16(&AS(c, ar + 64, ac), Ag + c * BKH + (size_t)64 * lda);
        cp_async16(&BS(c, ar, ac),      Bg + c * BKH);
        cp_async16(&BS(c, ar + 64, ac), Bg + c * BKH + (size_t)64 * ldb);
        asm volatile("cp.async.commit_group;\n" ::: "memory");
    }

    int cur = 0, nxt = STAGES - 1;
    for (int k = 0; k < NCH; k++) {
        asm volatile("cp.async.wait_group %0;\n" :: "n"(STAGES - 2) : "memory");
        __syncthreads();

        const int j = k + STAGES - 1;
        if (j < NCH) {
            cp_async16(&AS(nxt, ar, ac),      Ag + j * BKH);
            cp_async16(&AS(nxt, ar + 64, ac), Ag + j * BKH + (size_t)64 * lda);
            cp_async16(&BS(nxt, ar, ac),      Bg + j * BKH);
            cp_async16(&BS(nxt, ar + 64, ac), Bg + j * BKH + (size_t)64 * ldb);
        }
        asm volatile("cp.async.commit_group;\n" ::: "memory");

        const unsigned stage_off = cur * TILE_H * 2;
        #pragma unroll
        for (int kk = 0; kk < BKH; kk += 16) {
            unsigned af[4][4], bf[4][2];
            #pragma unroll
            for (int mt = 0; mt < 4; mt++)
                ldmatrix_x4(af[mt], aoff[mt] + stage_off + kk * 2);
            #pragma unroll
            for (int np = 0; np < 2; np++) {
                unsigned r[4];
                ldmatrix_x4(r, boff[np] + stage_off + kk * 2);
                bf[np * 2][0]     = r[0];
                bf[np * 2 + 1][0] = r[1];
                bf[np * 2][1]     = r[2];
                bf[np * 2 + 1][1] = r[3];
            }
            #pragma unroll
            for (int mt = 0; mt < 4; mt++)
                #pragma unroll
                for (int nt = 0; nt < 4; nt++)
                    mma_fp16(acc[mt][nt], af[mt], bf[nt]);
        }
        cur = (cur + 1 == STAGES) ? 0 : cur + 1;
        nxt = (nxt + 1 == STAGES) ? 0 : nxt + 1;
    }

    // epilogue
    #pragma unroll
    for (int mt = 0; mt < 4; mt++) {
        const int row0 = bm + m0 + mt * 16 + g;
        #pragma unroll
        for (int nt = 0; nt < 4; nt++) {
            const int col = bn + n0 + nt * 8 + 2 * t;
            const float bv0 = bias[col], bv1 = bias[col + 1];
            float v00 = acc[mt][nt][0] + bv0;
            float v01 = acc[mt][nt][1] + bv1;
            float v10 = acc[mt][nt][2] + bv0;
            float v11 = acc[mt][nt][3] + bv1;
            if (EPI == 1) {
                v00 = fminf((v00 > 20.f) ? v00 : log1pf(__expf(v00)), 1.0f);
                v01 = fminf((v01 > 20.f) ? v01 : log1pf(__expf(v01)), 1.0f);
                v10 = fminf((v10 > 20.f) ? v10 : log1pf(__expf(v10)), 1.0f);
                v11 = fminf((v11 > 20.f) ? v11 : log1pf(__expf(v11)), 1.0f);
            } else if (EPI == 2) {
                v00 += res[(size_t)row0 * ldres + col];
                v01 += res[(size_t)row0 * ldres + col + 1];
                v10 += res[(size_t)(row0 + 8) * ldres + col];
                v11 += res[(size_t)(row0 + 8) * ldres + col + 1];
            }
            if (OUTH) {
                __half* C = (__half*)Cv;
                *(__half2*)(C + (size_t)row0 * ldc + col)       = __floats2half2_rn(v00, v01);
                *(__half2*)(C + (size_t)(row0 + 8) * ldc + col) = __floats2half2_rn(v10, v11);
            } else {
                float* C = (float*)Cv;
                *(float2*)(C + (size_t)row0 * ldc + col)       = make_float2(v00, v01);
                *(float2*)(C + (size_t)(row0 + 8) * ldc + col) = make_float2(v10, v11);
            }
        }
    }
    #undef AS
    #undef BS
}

// -------------------- weight fp32 -> fp16 conversion ------------------------
__global__ void __launch_bounds__(256) cvt_kernel(
    const float4* __restrict__ src, __half* __restrict__ dst, int n4)
{
    int i = blockIdx.x * blockDim.x + threadIdx.x;
    int stride = gridDim.x * blockDim.x;
    for (; i < n4; i += stride) {
        float4 v = src[i];
        __half2 lo = __floats2half2_rn(v.x, v.y);
        __half2 hi = __floats2half2_rn(v.z, v.w);
        *(__half2*)(dst + i * 4)     = lo;
        *(__half2*)(dst + i * 4 + 2) = hi;
    }
}

// -------------------- LayerNorm (fp16 output) -------------------------------
__global__ void __launch_bounds__(256) ln_kernel(
    const float* __restrict__ x,
    const float* __restrict__ gamma,
    const float* __restrict__ beta,
    __half* __restrict__ out)
{
    const int token = blockIdx.x;
    const float* xp = x + (size_t)token * DIM;
    __half* op = out + (size_t)token * DIM;
    const int base = threadIdx.x * 8;

    float4 a = *(const float4*)(xp + base);
    float4 b = *(const float4*)(xp + base + 4);

    float s  = a.x + a.y + a.z + a.w + b.x + b.y + b.z + b.w;
    float ss = a.x*a.x + a.y*a.y + a.z*a.z + a.w*a.w
             + b.x*b.x + b.y*b.y + b.z*b.z + b.w*b.w;

    #pragma unroll
    for (int o = 16; o > 0; o >>= 1) {
        s  += __shfl_down_sync(0xffffffffu, s,  o);
        ss += __shfl_down_sync(0xffffffffu, ss, o);
    }
    __shared__ float sbuf[8], ssbuf[8];
    const int warp = threadIdx.x >> 5, lane = threadIdx.x & 31;
    if (lane == 0) { sbuf[warp] = s; ssbuf[warp] = ss; }
    __syncthreads();
    __shared__ float s_mean, s_rstd;
    if (threadIdx.x == 0) {
        float ts = 0.f, tss = 0.f;
        #pragma unroll
        for (int w = 0; w < 8; w++) { ts += sbuf[w]; tss += ssbuf[w]; }
        float mean = ts * (1.0f / DIM);
        float var  = tss * (1.0f / DIM) - mean * mean;
        s_mean = mean;
        s_rstd = rsqrtf(var + LN_EPS);
    }
    __syncthreads();
    const float mean = s_mean, rstd = s_rstd;

    float4 g0 = *(const float4*)(gamma + base);
    float4 g1 = *(const float4*)(gamma + base + 4);
    float4 bt0 = *(const float4*)(beta + base);
    float4 bt1 = *(const float4*)(beta + base + 4);

    __half2 h0 = __floats2half2_rn((a.x - mean) * rstd * g0.x + bt0.x,
                                   (a.y - mean) * rstd * g0.y + bt0.y);
    __half2 h1 = __floats2half2_rn((a.z - mean) * rstd * g0.z + bt0.z,
                                   (a.w - mean) * rstd * g0.w + bt0.w);
    __half2 h2 = __floats2half2_rn((b.x - mean) * rstd * g1.x + bt1.x,
                                   (b.y - mean) * rstd * g1.y + bt1.y);
    __half2 h3 = __floats2half2_rn((b.z - mean) * rstd * g1.z + bt1.z,
                                   (b.w - mean) * rstd * g1.w + bt1.w);
    uint4 pk;
    pk.x = *(unsigned*)&h0; pk.y = *(unsigned*)&h1;
    pk.z = *(unsigned*)&h2; pk.w = *(unsigned*)&h3;
    *(uint4*)(op + base) = pk;
}

// -------------------- fused B/C projection + SSM + gate ---------------------
__global__ void __launch_bounds__(256) bcssm_kernel(
    const __half* __restrict__ xz, int ld,
    const __half* __restrict__ dt,
    const float* __restrict__ A,
    const float* __restrict__ W_B, const float* __restrict__ b_B,
    const float* __restrict__ W_C, const float* __restrict__ b_C,
    __half* __restrict__ gated)
{
    __shared__ float xs[DIM];
    __shared__ float coef[NSTATE];
    const int token = blockIdx.x;
    const __half* xrow = xz + (size_t)token * ld;

    for (int d = threadIdx.x * 8; d < DIM; d += 256 * 8) {
        uint4 pk = *(const uint4*)(xrow + d);
        float2 f0 = __half22float2(*(__half2*)&pk.x);
        float2 f1 = __half22float2(*(__half2*)&pk.y);
        float2 f2 = __half22float2(*(__half2*)&pk.z);
        float2 f3 = __half22float2(*(__half2*)&pk.w);
        xs[d+0] = f0.x; xs[d+1] = f0.y; xs[d+2] = f1.x; xs[d+3] = f1.y;
        xs[d+4] = f2.x; xs[d+5] = f2.y; xs[d+6] = f3.x; xs[d+7] = f3.y;
    }
    __syncthreads();

    const int warp = threadIdx.x >> 5, lane = threadIdx.x & 31;
    const int n0 = warp * 2, n1 = n0 + 1;
    const float* wb0 = W_B + (size_t)n0 * DIM;
    const float* wb1 = W_B + (size_t)n1 * DIM;
    const float* wc0 = W_C + (size_t)n0 * DIM;
    const float* wc1 = W_C + (size_t)n1 * DIM;

    float sB0 = 0.f, sB1 = 0.f, sC0 = 0.f, sC1 = 0.f;
    for (int d = lane * 4; d < DIM; d += 128) {
        float4 xv  = *(const float4*)(xs + d);
        float4 vb0 = *(const float4*)(wb0 + d);
        float4 vb1 = *(const float4*)(wb1 + d);
        float4 vc0 = *(const float4*)(wc0 + d);
        float4 vc1 = *(const float4*)(wc1 + d);
        sB0 += xv.x*vb0.x + xv.y*vb0.y + xv.z*vb0.z + xv.w*vb0.w;
        sB1 += xv.x*vb1.x + xv.y*vb1.y + xv.z*vb1.z + xv.w*vb1.w;
        sC0 += xv.x*vc0.x + xv.y*vc0.y + xv.z*vc0.z + xv.w*vc0.w;
        sC1 += xv.x*vc1.x + xv.y*vc1.y + xv.z*vc1.z + xv.w*vc1.w;
    }
    #pragma unroll
    for (int o = 16; o > 0; o >>= 1) {
        sB0 += __shfl_down_sync(0xffffffffu, sB0, o);
        sB1 += __shfl_down_sync(0xffffffffu, sB1, o);
        sC0 += __shfl_down_sync(0xffffffffu, sC0, o);
        sC1 += __shfl_down_sync(0xffffffffu, sC1, o);
    }
    if (lane == 0) {
        coef[n0] = (sB0 + b_B[n0]) * (sC0 + b_C[n0]);
        coef[n1] = (sB1 + b_B[n1]) * (sC1 + b_C[n1]);
    }
    __syncthreads();

    float c[NSTATE];
    #pragma unroll
    for (int n = 0; n < NSTATE; n++) c[n] = coef[n];

    const __half* zrow = xrow + DIM;
    const __half* dtrow = dt + (size_t)token * DIM;
    __half* grow = gated + (size_t)token * DIM;

    for (int d = threadIdx.x; d < DIM; d += 256) {
        const float dtd = __half2float(dtrow[d]);
        float s = 0.f;
        #pragma unroll
        for (int n = 0; n < NSTATE; n++)
            s += c[n] * __expf(A[n * DIM + d] * dtd);
        const float xv = xs[d];
        const float zv = __half2float(zrow[d]);
        const float sig = 1.0f / (1.0f + __expf(-zv));
        grow[d] = __float2half_rn(s * xv * zv * sig);
    }
}

// -------------------- launch ------------------------------------------------
extern "C" void kernel_launch(void* const* d_in, const int* in_sizes, int n_in,
                              void* d_out, int out_size)
{
    const float* x        = (const float*)d_in[0];
    const float* ln_gamma = (const float*)d_in[1];
    const float* ln_beta  = (const float*)d_in[2];
    const float* W_in     = (const float*)d_in[3];
    const float* b_in     = (const float*)d_in[4];
    const float* state_A  = (const float*)d_in[5];
    const float* W_B      = (const float*)d_in[6];
    const float* b_B      = (const float*)d_in[7];
    const float* W_C      = (const float*)d_in[8];
    const float* b_C      = (const float*)d_in[9];
    const float* W_dt     = (const float*)d_in[10];
    const float* b_dt     = (const float*)d_in[11];
    const float* W_out    = (const float*)d_in[12];
    const float* b_out    = (const float*)d_in[13];
    float* out = (float*)d_out;

    __half *xn, *xz, *dt, *gated, *win, *wdt, *wout;
    cudaGetSymbolAddress((void**)&xn,    g_xn);
    cudaGetSymbolAddress((void**)&xz,    g_xz);
    cudaGetSymbolAddress((void**)&dt,    g_dt);
    cudaGetSymbolAddress((void**)&gated, g_gated);
    cudaGetSymbolAddress((void**)&win,   g_win);
    cudaGetSymbolAddress((void**)&wdt,   g_wdt);
    cudaGetSymbolAddress((void**)&wout,  g_wout);

    static bool attr_done = false;
    if (!attr_done) {
        cudaFuncSetAttribute(gemm_fp16<0,1>, cudaFuncAttributeMaxDynamicSharedMemorySize, SM_TOTAL_BYTES);
        cudaFuncSetAttribute(gemm_fp16<1,1>, cudaFuncAttributeMaxDynamicSharedMemorySize, SM_TOTAL_BYTES);
        cudaFuncSetAttribute(gemm_fp16<2,0>, cudaFuncAttributeMaxDynamicSharedMemorySize, SM_TOTAL_BYTES);
        attr_done = true;
    }

    // 0. convert weights to fp16
    cvt_kernel<<<1024, 256>>>((const float4*)W_in,  win,  TWO_DIM * DIM / 4);
    cvt_kernel<<<512,  256>>>((const float4*)W_dt,  wdt,  DIM * DIM / 4);
    cvt_kernel<<<512,  256>>>((const float4*)W_out, wout, DIM * DIM / 4);

    // 1. LayerNorm (fp16 output)
    ln_kernel<<<TOKENS, 256>>>(x, ln_gamma, ln_beta, xn);

    // 2. xz = xn @ W_in^T + b_in   (M=4096, N=4096, K=2048) -> fp16
    gemm_fp16<0, 1><<<dim3(TWO_DIM / BN, TOKENS / BM), 256, SM_TOTAL_BYTES>>>(
        xn, DIM, win, DIM, b_in, nullptr, 0, xz, TWO_DIM, DIM);

    // 3. dt = min(softplus(x_ssm @ W_dt^T + b_dt), 1)  -> fp16
    gemm_fp16<1, 1><<<dim3(DIM / BN, TOKENS / BM), 256, SM_TOTAL_BYTES>>>(
        xz, TWO_DIM, wdt, DIM, b_dt, nullptr, 0, dt, DIM, DIM);

    // 4+5. coef + gated fused -> fp16
    bcssm_kernel<<<TOKENS, 256>>>(xz, TWO_DIM, dt, state_A, W_B, b_B, W_C, b_C, gated);

    // 6. out = gated @ W_out^T + b_out + residual(x) -> fp32
    gemm_fp16<2, 0><<<dim3(DIM / BN, TOKENS / BM), 256, SM_TOTAL_BYTES>>>(
        gated, DIM, wout, DIM, b_out, x, DIM, out, DIM, DIM);
}